// round 9
// baseline (speedup 1.0000x reference)
#include <cuda_runtime.h>
#include <cstdint>

// Problem constants
#define NB   64
#define NT   2048
#define EMBD 32
#define HID  256
#define CSIZE  8              // cluster size = unit slices
#define BSLICE 16             // batch groups (one cluster each)
#define NCTA  (CSIZE * BSLICE)   // 128
#define UPC   32              // units per CTA
#define NROWS 128             // 4 gates x 32 units
#define BPC   4               // batches per CTA / cluster
#define NTHREADS 256

#define WPAD 292              // W row stride (floats): rows tile banks 4j; 16B-aligned
#define RPAD 36               // xe/hb/stage row stride (floats): 4-bank offset per batch

// SMEM float offsets
#define XE_F  (NROWS * WPAD)                    // 37376
#define HB_F  (XE_F + BPC * RPAD)               // 37520
#define ST_F  (HB_F + 2 * CSIZE * BPC * RPAD)   // 39824
#define GS_F  (ST_F + 2 * BPC * RPAD)           // 40112
#define BS_F  (GS_F + NROWS * BPC)              // 40624
#define LEN_F (BS_F + NROWS)                    // 40752
#define ML_F  (LEN_F + NB)                      // 40816
#define MB_F  (ML_F + 4)                        // 40820 (byte 163280, 16B aligned)
#define SM_FLOATS (MB_F + 8)

#define HB_BUF_B (CSIZE * BPC * RPAD * 4)       // 4608 B per hb buffer
#define ST_BUF_B (BPC * RPAD * 4)               // 576 B per staging buffer
#define TX_BYTES (CSIZE * ST_BUF_B)             // 4608 B expected per step

__device__ __forceinline__ float sigf(float x)  { return 1.0f / (1.0f + __expf(-x)); }
__device__ __forceinline__ float tanha(float x) { return 2.0f / (1.0f + __expf(-2.0f * x)) - 1.0f; }

#define LDS2U64(a, b, addr) \
    asm volatile("ld.shared.v2.u64 {%0,%1}, [%2];" : "=l"(a), "=l"(b) : "r"(addr))
#define FMA2(acc, w, z) \
    asm volatile("fma.rn.f32x2 %0, %1, %2, %0;" : "+l"(acc) : "l"(w), "l"(z))

#define MBARRIER_INIT(mbar, cnt) \
    asm volatile("mbarrier.init.shared.b64 [%0], %1;" :: "r"(mbar), "r"(cnt) : "memory")
#define MBARRIER_EXPECT_TX(mbar, tx) \
    asm volatile("mbarrier.arrive.expect_tx.shared.b64 _, [%0], %1;" :: "r"(mbar), "r"(tx) : "memory")
#define MBARRIER_WAIT_PARITY(mbar, ph) do {                                         \
    uint32_t _m = (mbar), _p = (ph), _done;                                         \
    asm volatile("{\n\t.reg .pred p;\n\t"                                           \
        "mbarrier.try_wait.parity.acquire.cta.shared::cta.b64 p, [%1], %2;\n\t"     \
        "selp.b32 %0, 1, 0, p;\n\t}"                                                \
        : "=r"(_done) : "r"(_m), "r"(_p) : "memory");                               \
    if (!_done) {                                                                   \
        asm volatile("{\n\t.reg .pred P1;\n\t"                                      \
            "WL_%=:\n\t"                                                            \
            "mbarrier.try_wait.parity.acquire.cta.shared::cta.b64 P1, [%0], %1, 0x989680;\n\t" \
            "@P1 bra.uni WD_%=;\n\t"                                                \
            "bra.uni WL_%=;\n\t"                                                    \
            "WD_%=:\n\t}"                                                           \
            :: "r"(_m), "r"(_p) : "memory");                                        \
    }                                                                               \
} while (0)

#define BULK_S2C(dst, src, bytes, mbar) \
    asm volatile("cp.async.bulk.shared::cluster.shared::cta.mbarrier::complete_tx::bytes " \
                 "[%0], [%1], %2, [%3];" \
                 :: "r"(dst), "r"(src), "r"(bytes), "r"(mbar) : "memory")

#define CLUSTER_SYNC() do { \
    asm volatile("barrier.cluster.arrive.aligned;" ::: "memory"); \
    asm volatile("barrier.cluster.wait.aligned;" ::: "memory"); \
} while (0)

__global__ void __launch_bounds__(NTHREADS, 1) __cluster_dims__(CSIZE, 1, 1)
lstm_tma_kernel(const int* __restrict__ x,        // [NB, NT]
                const int* __restrict__ lengths,  // [NB]
                const float* __restrict__ emb,    // [VOCAB, EMBD]
                const float* __restrict__ W_ih,   // [4*HID, EMBD]
                const float* __restrict__ W_hh,   // [4*HID, HID]
                const float* __restrict__ b_ih,   // [4*HID]
                const float* __restrict__ b_hh,   // [4*HID]
                float* __restrict__ out)          // [NB, 1, HID]
{
    extern __shared__ float sm[];

    const int tid = threadIdx.x;
    uint32_t us;
    asm("mov.u32 %0, %%cluster_ctarank;" : "=r"(us));
    const int bsl = blockIdx.x >> 3;          // batch group (cluster id)
    const int u0  = (int)us * UPC;
    const int bb0 = bsl * BPC;

    // ---- one-time staging: W rows (row = gate*32 + unit_local), biases ----
    for (int idx = tid; idx < NROWS * (EMBD + HID); idx += NTHREADS) {
        int r = idx / (EMBD + HID);
        int k = idx - r * (EMBD + HID);
        int g = r >> 5, du = r & 31;
        int grow = g * HID + u0 + du;
        float v = (k < EMBD) ? W_ih[grow * EMBD + k]
                             : W_hh[grow * HID + (k - EMBD)];
        sm[r * WPAD + k] = v;
    }
    if (tid < NROWS) {
        int g = tid >> 5, du = tid & 31;
        int grow = g * HID + u0 + du;
        sm[BS_F + tid] = b_ih[grow] + b_hh[grow];
    }
    if (tid < NB) ((int*)(sm + LEN_F))[tid] = lengths[tid];
    // zero both hb buffers (t=0 reads zeros)
    for (int i = tid; i < 2 * CSIZE * BPC * RPAD; i += NTHREADS) sm[HB_F + i] = 0.0f;
    __syncthreads();
    if (tid == 0) {
        int m = 1;
        for (int b = 0; b < NB; b++) m = max(m, ((int*)(sm + LEN_F))[b]);
        ((int*)(sm + ML_F))[0] = m;
    }
    // gather xe(0): tid<32 -> batch tid>>3, float4 q = tid&7
    if (tid < 32) {
        int b = tid >> 3, q = tid & 7;
        int tok = x[(bb0 + b) * NT + 0];
        float4 v = ((const float4*)(emb + (size_t)tok * EMBD))[q];
        *(float4*)(sm + XE_F + b * RPAD + q * 4) = v;
    }
    __syncthreads();
    const int maxlen = ((int*)(sm + ML_F))[0];

    // shared base
    uint32_t sb;
    asm("{ .reg .u64 t; cvta.to.shared.u64 t, %1; cvt.u32.u64 %0, t; }"
        : "=r"(sb) : "l"(sm));
    const uint32_t HB_B = sb + (uint32_t)(HB_F * 4);
    const uint32_t MB_B = sb + (uint32_t)(MB_F * 4);

    // init the two parity mbarriers (arrive count = 1: the expect_tx arm)
    if (tid == 0) {
        MBARRIER_INIT(MB_B + 0u, 1u);
        MBARRIER_INIT(MB_B + 8u, 1u);
    }
    __syncthreads();
    CLUSTER_SYNC();   // peers' mbarriers live before any complete_tx can arrive

    // per-sender mapa'd peer addresses (thread tid<8 sends to rank tid)
    uint32_t my_peer_hb = 0, my_peer_mb = 0;
    if (tid < CSIZE) {
        asm("mapa.shared::cluster.u32 %0, %1, %2;" : "=r"(my_peer_hb) : "r"(HB_B), "r"(tid));
        asm("mapa.shared::cluster.u32 %0, %1, %2;" : "=r"(my_peer_mb) : "r"(MB_B), "r"(tid));
    }

    // GEMM mapping: thread = (rp, b); rows rp and rp+64; one batch b
    const int rp = tid >> 2;                  // 0..63
    const int b  = tid & 3;                   // 0..3
    const uint32_t waddr0 = sb + (uint32_t)(rp * WPAD) * 4u;
    const uint32_t waddr1 = sb + (uint32_t)((rp + 64) * WPAD) * 4u;
    const uint32_t xeZ = sb + (uint32_t)(XE_F + b * RPAD) * 4u;
    const float bias0 = sm[BS_F + rp];
    const float bias1 = sm[BS_F + rp + 64];
    float* gout0 = sm + GS_F + rp * BPC + b;
    float* gout1 = sm + GS_F + (rp + 64) * BPC + b;

    // phase-2 mapping (tid < 128): unit u_l, batch b2
    const int u_l = tid & 31;
    const int b2  = (tid >> 5) & 3;
    const int bg  = bb0 + b2;
    const int uu  = u0 + u_l;
    const int mylen = ((int*)(sm + LEN_F))[bg];
    float c_r = 0.0f, h_r = 0.0f;

    unsigned long long A0, A1;
    const unsigned long long bias_pk0 = (unsigned long long)__float_as_uint(bias0);
    const unsigned long long bias_pk1 = (unsigned long long)__float_as_uint(bias1);

    // ---- prologue: acc = bias + W_ih . xe(0) ----
    A0 = bias_pk0; A1 = bias_pk1;
    #pragma unroll
    for (int k = 0; k < EMBD; k += 4) {
        unsigned long long Wa, Wb, Va, Vb, Za, Zb;
        LDS2U64(Wa, Wb, waddr0 + k * 4);
        LDS2U64(Va, Vb, waddr1 + k * 4);
        LDS2U64(Za, Zb, xeZ + k * 4);
        FMA2(A0, Wa, Za); FMA2(A0, Wb, Zb);
        FMA2(A1, Va, Za); FMA2(A1, Vb, Zb);
    }

    int ph0 = 0, ph1 = 0;   // parity cursors for mbar[0], mbar[1]

    for (int t = 0; t < maxlen; t++) {
        // ---- wait for all 8 peers' h(t-1) fragments (HW-sleep) ----
        if (t > 0) {
            if (t & 1) { MBARRIER_WAIT_PARITY(MB_B + 8u, (uint32_t)ph1); ph1 ^= 1; }
            else       { MBARRIER_WAIT_PARITY(MB_B + 0u, (uint32_t)ph0); ph0 ^= 1; }
        }
        // arm the barrier that step-t sends will target
        if (tid == 0 && t + 1 < maxlen) {
            MBARRIER_EXPECT_TX(MB_B + (uint32_t)(((t + 1) & 1) * 8), (uint32_t)TX_BYTES);
        }

        // ---- acc += W_hh . h(t-1) from local hb[t&1] ----
        {
            const uint32_t zbb = HB_B + (uint32_t)((t & 1) * HB_BUF_B + b * RPAD * 4);
            #pragma unroll
            for (int r = 0; r < CSIZE; r++) {
                const uint32_t wk0 = waddr0 + (uint32_t)((EMBD + r * 32) * 4);
                const uint32_t wk1 = waddr1 + (uint32_t)((EMBD + r * 32) * 4);
                const uint32_t zr  = zbb + (uint32_t)(r * BPC * RPAD * 4);
                #pragma unroll
                for (int kk = 0; kk < 32; kk += 4) {
                    unsigned long long Wa, Wb, Va, Vb, Za, Zb;
                    LDS2U64(Wa, Wb, wk0 + kk * 4);
                    LDS2U64(Va, Vb, wk1 + kk * 4);
                    LDS2U64(Za, Zb, zr + kk * 4);
                    FMA2(A0, Wa, Za); FMA2(A0, Wb, Zb);
                    FMA2(A1, Va, Za); FMA2(A1, Vb, Zb);
                }
            }
        }
        // gate = lo + hi of k-split accumulators
        {
            float g0 = __uint_as_float((uint32_t)A0) + __uint_as_float((uint32_t)(A0 >> 32));
            float g1 = __uint_as_float((uint32_t)A1) + __uint_as_float((uint32_t)(A1 >> 32));
            *gout0 = g0;
            *gout1 = g1;
        }
        __syncthreads();

        // ---- phase 2 (tid < 128): activations + state update -> staging ----
        if (tid < 128) {
            float gi = sm[GS_F + (0 * 32 + u_l) * BPC + b2];
            float gf = sm[GS_F + (1 * 32 + u_l) * BPC + b2];
            float gg = sm[GS_F + (2 * 32 + u_l) * BPC + b2];
            float go = sm[GS_F + (3 * 32 + u_l) * BPC + b2];
            float iv = sigf(gi), fv = sigf(gf), gv = tanha(gg), ov = sigf(go);
            float cn = fmaf(fv, c_r, iv * gv);
            float hn = ov * tanha(cn);
            if (t < mylen) { c_r = cn; h_r = hn; }
            sm[ST_F + (t & 1) * BPC * RPAD + b2 * RPAD + u_l] = h_r;
        }
        __syncthreads();   // staging complete CTA-wide

        if (t + 1 < maxlen) {
            // ---- async bulk push: my 576B fragment -> all 8 peers' hb[(t+1)&1] ----
            if (tid < CSIZE) {
                asm volatile("fence.proxy.async.shared::cta;" ::: "memory");
                uint32_t dst = my_peer_hb + (uint32_t)(((t + 1) & 1) * HB_BUF_B + (int)us * ST_BUF_B);
                uint32_t mb  = my_peer_mb + (uint32_t)(((t + 1) & 1) * 8);
                uint32_t src = sb + (uint32_t)(ST_F * 4 + (t & 1) * ST_BUF_B);
                BULK_S2C(dst, src, (uint32_t)ST_BUF_B, mb);
            }
            // ---- overlap with in-flight copies: xe(t+1) gather + input GEMM ----
            if (tid < 32) {
                int bb = tid >> 3, q = tid & 7;
                int tok = x[(bb0 + bb) * NT + (t + 1)];
                float4 v = ((const float4*)(emb + (size_t)tok * EMBD))[q];
                *(float4*)(sm + XE_F + bb * RPAD + q * 4) = v;
            }
            __syncthreads();
            A0 = bias_pk0; A1 = bias_pk1;
            #pragma unroll
            for (int k = 0; k < EMBD; k += 4) {
                unsigned long long Wa, Wb, Va, Vb, Za, Zb;
                LDS2U64(Wa, Wb, waddr0 + k * 4);
                LDS2U64(Va, Vb, waddr1 + k * 4);
                LDS2U64(Za, Zb, xeZ + k * 4);
                FMA2(A0, Wa, Za); FMA2(A0, Wb, Zb);
                FMA2(A1, Va, Za); FMA2(A1, Vb, Zb);
            }
        }
    }

    // final frozen h == reference out[:, -1, :]
    if (tid < 128) out[bg * HID + uu] = h_r;

    // no CTA exits while cluster peers may still interact
    CLUSTER_SYNC();
}

extern "C" void kernel_launch(void* const* d_in, const int* in_sizes, int n_in,
                              void* d_out, int out_size) {
    const int*   x       = (const int*)d_in[0];
    const int*   lengths = (const int*)d_in[1];
    const float* emb     = (const float*)d_in[2];
    const float* W_ih    = (const float*)d_in[3];
    const float* W_hh    = (const float*)d_in[4];
    const float* b_ih    = (const float*)d_in[5];
    const float* b_hh    = (const float*)d_in[6];
    float* out = (float*)d_out;

    const int smem_bytes = SM_FLOATS * (int)sizeof(float) + 64;

    cudaFuncSetAttribute(lstm_tma_kernel,
                         cudaFuncAttributeMaxDynamicSharedMemorySize, smem_bytes);

    lstm_tma_kernel<<<NCTA, NTHREADS, smem_bytes>>>(
        x, lengths, emb, W_ih, W_hh, b_ih, b_hh, out);
}

// round 10
// speedup vs baseline: 1.2903x; 1.2903x over previous
#include <cuda_runtime.h>
#include <cstdint>

// Problem constants
#define NB   64
#define NT   2048
#define EMBD 32
#define HID  256
#define KTOT (EMBD + HID)    // 288
#define USLICE 32
#define BSLICE 4
#define NCTA  (USLICE * BSLICE)   // 128
#define UPC   8              // units per CTA
#define NROWS (4 * UPC)      // 32 gate rows
#define BPC   16             // batches per CTA
#define NTHREADS 64          // 2 warps; thread tile 4 rows x 2 batches (RB=8)

#define WJ   292             // j (row-within-group) stride, floats
#define WRG  1176            // rg (4-row group) stride = 4*292+8; %32==24 -> distinct quads
#define ZPAD 292             // z row stride; %32==4 -> 8 batch loads tile all 32 banks

// Persistent cross-CTA state
__device__ float g_H[2][NB * HID];        // [buf][batch*HID + unit]
__device__ int   g_flag[BSLICE][USLICE];  // steps completed by producer (us,bsl)

__global__ void lstm_init_kernel() {
    int i = threadIdx.x;
    if (i < BSLICE * USLICE) ((int*)g_flag)[i] = 0;
}

__device__ __forceinline__ float sigf(float x)  { return 1.0f / (1.0f + __expf(-x)); }
__device__ __forceinline__ float tanha(float x) { return 2.0f / (1.0f + __expf(-2.0f * x)) - 1.0f; }

__device__ __forceinline__ int ld_acq(const int* p) {
    int v;
    asm volatile("ld.acquire.gpu.b32 %0, [%1];" : "=r"(v) : "l"(p));
    return v;
}

#define LDS2U64(a, b, addr) \
    asm volatile("ld.shared.v2.u64 {%0,%1}, [%2];" : "=l"(a), "=l"(b) : "r"(addr))
#define FMA2(acc, w, z) \
    asm volatile("fma.rn.f32x2 %0, %1, %2, %0;" : "+l"(acc) : "l"(w), "l"(z))

__global__ void __launch_bounds__(NTHREADS, 1)
lstm_persist_kernel(const int* __restrict__ x,        // [NB, NT]
                    const int* __restrict__ lengths,  // [NB]
                    const float* __restrict__ emb,    // [VOCAB, EMBD]
                    const float* __restrict__ W_ih,   // [4*HID, EMBD]
                    const float* __restrict__ W_hh,   // [4*HID, HID]
                    const float* __restrict__ b_ih,   // [4*HID]
                    const float* __restrict__ b_hh,   // [4*HID]
                    float* __restrict__ out)          // [NB, 1, HID]
{
    extern __shared__ float sm[];
    // w: [rg 0..7][j 0..3][k 0..287], rg stride WRG, j stride WJ
    float* w_s  = sm;                        // 7*1176+3*292+288 = 9396 floats
    float* z_s  = w_s + 9408;                // [BPC][ZPAD]  k: 0..31 xe, 32..287 h
    float* gs   = z_s + BPC * ZPAD;          // [NROWS][BPC]
    float* bs   = gs + NROWS * BPC;          // [NROWS]
    int* lenS   = (int*)(bs + NROWS);        // [NB]
    int* mlS    = lenS + NB;

    const int tid = threadIdx.x;
    const int cta = blockIdx.x;
    const int us  = cta >> 2;
    const int bsl = cta & 3;
    const int u0  = us * UPC;
    const int bb0 = bsl * BPC;

    // ---- one-time staging: W (row r -> [r>>2][r&3][k]), biases, lengths ----
    for (int idx = tid; idx < NROWS * KTOT; idx += NTHREADS) {
        int r = idx / KTOT;
        int k = idx - r * KTOT;
        int g = r >> 3, du = r & 7;          // row convention: r = g*8 + du
        int grow = g * HID + u0 + du;
        float v = (k < EMBD) ? W_ih[grow * EMBD + k]
                             : W_hh[grow * HID + (k - EMBD)];
        w_s[(r >> 2) * WRG + (r & 3) * WJ + k] = v;
    }
    if (tid < NROWS) {
        int g = tid >> 3, du = tid & 7;
        int grow = g * HID + u0 + du;
        bs[tid] = b_ih[grow] + b_hh[grow];
    }
    if (tid < NB) lenS[tid] = lengths[tid];
    __syncthreads();
    if (tid == 0) {
        int m = 1;
        for (int b = 0; b < NB; b++) m = max(m, lenS[b]);
        *mlS = m;
    }
    // zero h region of z (t=0 reads zeros)
    for (int i = tid; i < BPC * HID; i += NTHREADS) {
        int b = i >> 8, u = i & 255;
        z_s[b * ZPAD + EMBD + u] = 0.0f;
    }
    // gather xe(0)
    if (tid < BPC) {
        int tok = x[(bb0 + tid) * NT + 0];
        const float4* e = (const float4*)(emb + (long)tok * EMBD);
        float4* zr = (float4*)(z_s + tid * ZPAD);
        #pragma unroll
        for (int q = 0; q < EMBD / 4; q++) zr[q] = e[q];
    }
    __syncthreads();
    const int maxlen = *mlS;

    // shared base for asm addressing
    uint32_t sb;
    asm("{ .reg .u64 t; cvta.to.shared.u64 t, %1; cvt.u32.u64 %0, t; }"
        : "=r"(sb) : "l"(sm));
    const uint32_t ZOFF = 9408u * 4u;

    // GEMM mapping: 64 threads = 8 row-groups x 8 batch-slots
    const int rg = tid >> 3;                 // rows 4rg..4rg+3
    const int bq = tid & 7;                  // batches bq, bq+8
    const uint32_t wb = sb + (uint32_t)(rg * WRG) * 4u;    // + j*WJ*4 + k*4
    const uint32_t zA = sb + ZOFF + (uint32_t)(bq * ZPAD) * 4u;
    const uint32_t zB = zA + (uint32_t)(8 * ZPAD) * 4u;
    float biasj[4];
    #pragma unroll
    for (int j = 0; j < 4; j++) biasj[j] = bs[4 * rg + j];

    // phase-2 mapping: pairs p = tid, tid+64 -> (u_l = p>>4, b2 = p&15)
    const int uA_l = tid >> 4,        bA = tid & 15;
    const int uB_l = (tid + 64) >> 4, bB = (tid + 64) & 15;
    const int bgA = bb0 + bA, bgB = bb0 + bB;
    const int uuA = u0 + uA_l, uuB = u0 + uB_l;
    const int lenA = lenS[bgA], lenB = lenS[bgB];
    float cA = 0.f, hA = 0.f, cB = 0.f, hB = 0.f;

    unsigned long long A[4][2];
    #pragma unroll
    for (int j = 0; j < 4; j++) {
        unsigned long long bp = (unsigned long long)__float_as_uint(biasj[j]);
        A[j][0] = bp; A[j][1] = bp;
    }

    // ---- prologue: acc = bias + W_ih . xe(0) ----
    #pragma unroll
    for (int k = 0; k < EMBD; k += 4) {
        unsigned long long Z01a, Z23a, Z01b, Z23b;
        LDS2U64(Z01a, Z23a, zA + k * 4);
        LDS2U64(Z01b, Z23b, zB + k * 4);
        #pragma unroll
        for (int j = 0; j < 4; j++) {
            unsigned long long W01, W23;
            LDS2U64(W01, W23, wb + (uint32_t)(j * WJ + k) * 4u);
            FMA2(A[j][0], W01, Z01a); FMA2(A[j][0], W23, Z23a);
            FMA2(A[j][1], W01, Z01b); FMA2(A[j][1], W23, Z23b);
        }
    }

    for (int t = 0; t < maxlen; t++) {
        if (t > 0) {
            // ---- wait for same-bsl producers to publish h(t-1) ----
            if (tid < USLICE) {
                const int* f = &g_flag[bsl][tid];
                if (ld_acq(f) < t) {
                    do { __nanosleep(64); } while (ld_acq(f) < t);
                }
            }
            __syncthreads();
            // ---- stage h(t-1): volatile (L1-bypassing) loads ----
            const float4* src = (const float4*)(g_H[t & 1] + bb0 * HID);
            #pragma unroll
            for (int i = 0; i < (BPC * HID / 4) / NTHREADS; i++) {
                int idx = i * NTHREADS + tid;
                float4 v;
                asm volatile("ld.volatile.global.v4.f32 {%0,%1,%2,%3}, [%4];"
                             : "=f"(v.x), "=f"(v.y), "=f"(v.z), "=f"(v.w)
                             : "l"(src + idx));
                int b = idx >> 6;
                int u4 = (idx & 63) * 4;
                *(float4*)(z_s + b * ZPAD + EMBD + u4) = v;
            }
            __syncthreads();
        }

        // ---- acc += W_hh . h  (k = 32..287), 4 rows x 2 batches per thread ----
        {
            const uint32_t zkA = zA + EMBD * 4;
            const uint32_t zkB = zB + EMBD * 4;
            const uint32_t wk  = wb + EMBD * 4;
            #pragma unroll 2
            for (int k = 0; k < HID; k += 4) {
                unsigned long long Z01a, Z23a, Z01b, Z23b;
                LDS2U64(Z01a, Z23a, zkA + k * 4);
                LDS2U64(Z01b, Z23b, zkB + k * 4);
                #pragma unroll
                for (int j = 0; j < 4; j++) {
                    unsigned long long W01, W23;
                    LDS2U64(W01, W23, wk + (uint32_t)(j * WJ + k) * 4u);
                    FMA2(A[j][0], W01, Z01a); FMA2(A[j][0], W23, Z23a);
                    FMA2(A[j][1], W01, Z01b); FMA2(A[j][1], W23, Z23b);
                }
            }
        }
        // gate = lo + hi of each k-split accumulator
        #pragma unroll
        for (int j = 0; j < 4; j++) {
            float ga = __uint_as_float((uint32_t)A[j][0]) +
                       __uint_as_float((uint32_t)(A[j][0] >> 32));
            float gb = __uint_as_float((uint32_t)A[j][1]) +
                       __uint_as_float((uint32_t)(A[j][1] >> 32));
            gs[(4 * rg + j) * BPC + bq]     = ga;
            gs[(4 * rg + j) * BPC + bq + 8] = gb;
        }
        __syncthreads();

        // ---- phase 2: two (unit,batch) pairs per thread ----
        {
            float gi = gs[(0 * UPC + uA_l) * BPC + bA];
            float gf = gs[(1 * UPC + uA_l) * BPC + bA];
            float gg = gs[(2 * UPC + uA_l) * BPC + bA];
            float go = gs[(3 * UPC + uA_l) * BPC + bA];
            float iv = sigf(gi), fv = sigf(gf), gv = tanha(gg), ov = sigf(go);
            float cn = fmaf(fv, cA, iv * gv);
            float hn = ov * tanha(cn);
            if (t < lenA) { cA = cn; hA = hn; }
            g_H[(t + 1) & 1][bgA * HID + uuA] = hA;

            gi = gs[(0 * UPC + uB_l) * BPC + bB];
            gf = gs[(1 * UPC + uB_l) * BPC + bB];
            gg = gs[(2 * UPC + uB_l) * BPC + bB];
            go = gs[(3 * UPC + uB_l) * BPC + bB];
            iv = sigf(gi); fv = sigf(gf); gv = tanha(gg); ov = sigf(go);
            cn = fmaf(fv, cB, iv * gv);
            hn = ov * tanha(cn);
            if (t < lenB) { cB = cn; hB = hn; }
            g_H[(t + 1) & 1][bgB * HID + uuB] = hB;
        }
        __syncthreads();   // all g_H stores issued CTA-wide

        // ---- publish: this CTA finished step t ----
        if (tid == 0) {
            __threadfence();                 // release h stores to gpu scope
            g_flag[bsl][us] = t + 1;
        }

        if (t + 1 < maxlen) {
            // overlap with other CTAs: gather xe(t+1)
            if (tid < BPC) {
                int tok = x[(bb0 + tid) * NT + (t + 1)];
                const float4* e = (const float4*)(emb + (long)tok * EMBD);
                float4* zr = (float4*)(z_s + tid * ZPAD);
                #pragma unroll
                for (int q = 0; q < EMBD / 4; q++) zr[q] = e[q];
            }
            __syncthreads();
            // overlap: input-projection GEMM for t+1
            #pragma unroll
            for (int j = 0; j < 4; j++) {
                unsigned long long bp = (unsigned long long)__float_as_uint(biasj[j]);
                A[j][0] = bp; A[j][1] = bp;
            }
            #pragma unroll
            for (int k = 0; k < EMBD; k += 4) {
                unsigned long long Z01a, Z23a, Z01b, Z23b;
                LDS2U64(Z01a, Z23a, zA + k * 4);
                LDS2U64(Z01b, Z23b, zB + k * 4);
                #pragma unroll
                for (int j = 0; j < 4; j++) {
                    unsigned long long W01, W23;
                    LDS2U64(W01, W23, wb + (uint32_t)(j * WJ + k) * 4u);
                    FMA2(A[j][0], W01, Z01a); FMA2(A[j][0], W23, Z23a);
                    FMA2(A[j][1], W01, Z01b); FMA2(A[j][1], W23, Z23b);
                }
            }
        }
    }

    // final frozen h == reference out[:, -1, :]
    out[bgA * HID + uuA] = hA;
    out[bgB * HID + uuB] = hB;
}

extern "C" void kernel_launch(void* const* d_in, const int* in_sizes, int n_in,
                              void* d_out, int out_size) {
    const int*   x       = (const int*)d_in[0];
    const int*   lengths = (const int*)d_in[1];
    const float* emb     = (const float*)d_in[2];
    const float* W_ih    = (const float*)d_in[3];
    const float* W_hh    = (const float*)d_in[4];
    const float* b_ih    = (const float*)d_in[5];
    const float* b_hh    = (const float*)d_in[6];
    float* out = (float*)d_out;

    const int smem_bytes =
        (9408 + BPC * ZPAD + NROWS * BPC + NROWS) * (int)sizeof(float)
        + (NB + 1) * (int)sizeof(int) + 32;

    cudaFuncSetAttribute(lstm_persist_kernel,
                         cudaFuncAttributeMaxDynamicSharedMemorySize, smem_bytes);

    lstm_init_kernel<<<1, 128>>>();
    lstm_persist_kernel<<<NCTA, NTHREADS, smem_bytes>>>(
        x, lengths, emb, W_ih, W_hh, b_ih, b_hh, out);
}

// round 11
// speedup vs baseline: 1.7595x; 1.3636x over previous
#include <cuda_runtime.h>
#include <cstdint>

// Problem constants
#define NB   64
#define NT   2048
#define EMBD 32
#define HID  256
#define KTOT (EMBD + HID)    // 288
#define USLICE 32
#define BSLICE 4
#define NCTA  (USLICE * BSLICE)   // 128
#define UPC   8              // units per CTA
#define NROWS (4 * UPC)      // 32 gate rows
#define BPC   16             // batches per CTA
#define NTHREADS 256         // 4 k-segments x 64 threads (8 rg x 8 bq)
#define NSEG 4
#define SEGK 64              // k-values per segment (of the 256 h k's)

#define WJ   292             // j (row-within-group) stride, floats
#define WRG  1176            // rg (4-row group) stride; %32==24
#define ZPAD 292             // z row stride; %32==4 -> 8 batch loads tile all banks
#define GSTR 17              // gs_p row stride (floats)
#define GSEG (NROWS * GSTR)  // 544 floats per segment

// Persistent cross-CTA state
__device__ float g_H[2][NB * HID];        // [buf][batch*HID + unit]
__device__ int   g_flag[BSLICE][USLICE];  // steps completed by producer (us,bsl)

__global__ void lstm_init_kernel() {
    int i = threadIdx.x;
    if (i < BSLICE * USLICE) ((int*)g_flag)[i] = 0;
}

__device__ __forceinline__ float sigf(float x)  { return 1.0f / (1.0f + __expf(-x)); }
__device__ __forceinline__ float tanha(float x) { return 2.0f / (1.0f + __expf(-2.0f * x)) - 1.0f; }

__device__ __forceinline__ int ld_acq(const int* p) {
    int v;
    asm volatile("ld.acquire.gpu.b32 %0, [%1];" : "=r"(v) : "l"(p));
    return v;
}

#define LDS2U64(a, b, addr) \
    asm volatile("ld.shared.v2.u64 {%0,%1}, [%2];" : "=l"(a), "=l"(b) : "r"(addr))
#define FMA2(acc, w, z) \
    asm volatile("fma.rn.f32x2 %0, %1, %2, %0;" : "+l"(acc) : "l"(w), "l"(z))

__global__ void __launch_bounds__(NTHREADS, 1)
lstm_persist_kernel(const int* __restrict__ x,        // [NB, NT]
                    const int* __restrict__ lengths,  // [NB]
                    const float* __restrict__ emb,    // [VOCAB, EMBD]
                    const float* __restrict__ W_ih,   // [4*HID, EMBD]
                    const float* __restrict__ W_hh,   // [4*HID, HID]
                    const float* __restrict__ b_ih,   // [4*HID]
                    const float* __restrict__ b_hh,   // [4*HID]
                    float* __restrict__ out)          // [NB, 1, HID]
{
    extern __shared__ float sm[];
    // w: [rg 0..7][j 0..3][k 0..287]
    float* w_s  = sm;                        // 9408 floats
    float* z_s  = w_s + 9408;                // [BPC][ZPAD]  k: 0..31 xe, 32..287 h
    float* gp   = z_s + BPC * ZPAD;          // [NSEG][NROWS][GSTR] partial gates
    float* bs   = gp + NSEG * GSEG;          // [NROWS]
    int* lenS   = (int*)(bs + NROWS);        // [NB]
    int* mlS    = lenS + NB;

    const int tid = threadIdx.x;
    const int cta = blockIdx.x;
    const int us  = cta >> 2;
    const int bsl = cta & 3;
    const int u0  = us * UPC;
    const int bb0 = bsl * BPC;

    // ---- one-time staging ----
    for (int idx = tid; idx < NROWS * KTOT; idx += NTHREADS) {
        int r = idx / KTOT;
        int k = idx - r * KTOT;
        int g = r >> 3, du = r & 7;          // row r = g*8 + du
        int grow = g * HID + u0 + du;
        float v = (k < EMBD) ? W_ih[grow * EMBD + k]
                             : W_hh[grow * HID + (k - EMBD)];
        w_s[(r >> 2) * WRG + (r & 3) * WJ + k] = v;
    }
    if (tid < NROWS) {
        int g = tid >> 3, du = tid & 7;
        int grow = g * HID + u0 + du;
        bs[tid] = b_ih[grow] + b_hh[grow];
    }
    if (tid < NB) lenS[tid] = lengths[tid];
    __syncthreads();
    if (tid == 0) {
        int m = 1;
        for (int b = 0; b < NB; b++) m = max(m, lenS[b]);
        *mlS = m;
    }
    // zero h region of z (t=0 reads zeros)
    for (int i = tid; i < BPC * HID; i += NTHREADS) {
        int b = i >> 8, u = i & 255;
        z_s[b * ZPAD + EMBD + u] = 0.0f;
    }
    // gather xe(0)
    if (tid < BPC) {
        int tok = x[(bb0 + tid) * NT + 0];
        const float4* e = (const float4*)(emb + (long)tok * EMBD);
        float4* zr = (float4*)(z_s + tid * ZPAD);
        #pragma unroll
        for (int q = 0; q < EMBD / 4; q++) zr[q] = e[q];
    }
    __syncthreads();
    const int maxlen = *mlS;

    // shared base for asm addressing
    uint32_t sb;
    asm("{ .reg .u64 t; cvta.to.shared.u64 t, %1; cvt.u32.u64 %0, t; }"
        : "=r"(sb) : "l"(sm));
    const uint32_t ZOFF = 9408u * 4u;

    // GEMM mapping: tid = seg*64 + (rg*8 + bq)
    const int seg = tid >> 6;                // 0..3 -> k range EMBD+64*seg ..
    const int rg  = (tid >> 3) & 7;          // rows 4rg..4rg+3
    const int bq  = tid & 7;                 // batches bq, bq+8
    const uint32_t wbase = sb + (uint32_t)(rg * WRG) * 4u;
    const uint32_t wk    = wbase + (uint32_t)(EMBD + seg * SEGK) * 4u;
    const uint32_t zA    = sb + ZOFF + (uint32_t)(bq * ZPAD) * 4u;
    const uint32_t zB    = zA + (uint32_t)(8 * ZPAD) * 4u;
    const uint32_t zkA   = zA + (uint32_t)(EMBD + seg * SEGK) * 4u;
    const uint32_t zkB   = zB + (uint32_t)(EMBD + seg * SEGK) * 4u;
    float* gpb = gp + seg * GSEG;            // my partial plane

    // phase-2 mapping (tid < 128): one (unit,batch)
    const int u_l = tid >> 4;                // 0..7 (valid when tid<128)
    const int b2  = tid & 15;
    const int bg  = bb0 + b2;
    const int uu  = u0 + (u_l & 7);
    const int mylen = lenS[bg];
    float c_r = 0.0f, h_r = 0.0f;

    unsigned long long A[4][2];
    #pragma unroll
    for (int j = 0; j < 4; j++) { A[j][0] = 0ull; A[j][1] = 0ull; }

    // ---- prologue: seg0 accumulates W_ih . xe(0) (others stay zero) ----
    if (seg == 0) {
        #pragma unroll
        for (int k = 0; k < EMBD; k += 4) {
            unsigned long long Z01a, Z23a, Z01b, Z23b;
            LDS2U64(Z01a, Z23a, zA + k * 4);
            LDS2U64(Z01b, Z23b, zB + k * 4);
            #pragma unroll
            for (int j = 0; j < 4; j++) {
                unsigned long long W01, W23;
                LDS2U64(W01, W23, wbase + (uint32_t)(j * WJ + k) * 4u);
                FMA2(A[j][0], W01, Z01a); FMA2(A[j][0], W23, Z23a);
                FMA2(A[j][1], W01, Z01b); FMA2(A[j][1], W23, Z23b);
            }
        }
    }

    for (int t = 0; t < maxlen; t++) {
        if (t > 0) {
            // ---- wait for same-bsl producers to publish h(t-1) ----
            if (tid < USLICE) {
                const int* f = &g_flag[bsl][tid];
                if (ld_acq(f) < t) {
                    do { __nanosleep(32); } while (ld_acq(f) < t);
                }
            }
            __syncthreads();
            // ---- stage h(t-1): 4 volatile float4 loads per thread ----
            const float4* src = (const float4*)(g_H[t & 1] + bb0 * HID);
            #pragma unroll
            for (int i = 0; i < (BPC * HID / 4) / NTHREADS; i++) {
                int idx = i * NTHREADS + tid;
                float4 v;
                asm volatile("ld.volatile.global.v4.f32 {%0,%1,%2,%3}, [%4];"
                             : "=f"(v.x), "=f"(v.y), "=f"(v.z), "=f"(v.w)
                             : "l"(src + idx));
                int b = idx >> 6;
                int u4 = (idx & 63) * 4;
                *(float4*)(z_s + b * ZPAD + EMBD + u4) = v;
            }
            __syncthreads();
        }

        // ---- partial acc += W_hh . h over my 64-k segment ----
        #pragma unroll 4
        for (int k = 0; k < SEGK; k += 4) {
            unsigned long long Z01a, Z23a, Z01b, Z23b;
            LDS2U64(Z01a, Z23a, zkA + k * 4);
            LDS2U64(Z01b, Z23b, zkB + k * 4);
            #pragma unroll
            for (int j = 0; j < 4; j++) {
                unsigned long long W01, W23;
                LDS2U64(W01, W23, wk + (uint32_t)(j * WJ + k) * 4u);
                FMA2(A[j][0], W01, Z01a); FMA2(A[j][0], W23, Z23a);
                FMA2(A[j][1], W01, Z01b); FMA2(A[j][1], W23, Z23b);
            }
        }
        // write partial gate sums (lo+hi of k-split accumulators)
        #pragma unroll
        for (int j = 0; j < 4; j++) {
            float ga = __uint_as_float((uint32_t)A[j][0]) +
                       __uint_as_float((uint32_t)(A[j][0] >> 32));
            float gb = __uint_as_float((uint32_t)A[j][1]) +
                       __uint_as_float((uint32_t)(A[j][1] >> 32));
            gpb[(4 * rg + j) * GSTR + bq]     = ga;
            gpb[(4 * rg + j) * GSTR + bq + 8] = gb;
        }
        __syncthreads();

        // ---- phase 2 (tid < 128): reduce 4 partials + bias, activations ----
        if (tid < 128) {
            float gate[4];
            #pragma unroll
            for (int g = 0; g < 4; g++) {
                int r = g * UPC + u_l;
                float s = bs[r];
                #pragma unroll
                for (int sg = 0; sg < NSEG; sg++)
                    s += gp[sg * GSEG + r * GSTR + b2];
                gate[g] = s;
            }
            float iv = sigf(gate[0]), fv = sigf(gate[1]);
            float gv = tanha(gate[2]), ov = sigf(gate[3]);
            float cn = fmaf(fv, c_r, iv * gv);
            float hn = ov * tanha(cn);
            if (t < mylen) { c_r = cn; h_r = hn; }
            g_H[(t + 1) & 1][bg * HID + uu] = h_r;
        }
        __syncthreads();   // all g_H stores issued CTA-wide

        // ---- publish: release-store orders prior global writes ----
        if (tid == 0) {
            asm volatile("st.release.gpu.b32 [%0], %1;"
                         :: "l"(&g_flag[bsl][us]), "r"(t + 1) : "memory");
        }

        if (t + 1 < maxlen) {
            // overlap: gather xe(t+1)
            if (tid < BPC) {
                int tok = x[(bb0 + tid) * NT + (t + 1)];
                const float4* e = (const float4*)(emb + (long)tok * EMBD);
                float4* zr = (float4*)(z_s + tid * ZPAD);
                #pragma unroll
                for (int q = 0; q < EMBD / 4; q++) zr[q] = e[q];
            }
            __syncthreads();
            // reset partial accumulators; seg0 folds in the xe GEMM for t+1
            #pragma unroll
            for (int j = 0; j < 4; j++) { A[j][0] = 0ull; A[j][1] = 0ull; }
            if (seg == 0) {
                #pragma unroll
                for (int k = 0; k < EMBD; k += 4) {
                    unsigned long long Z01a, Z23a, Z01b, Z23b;
                    LDS2U64(Z01a, Z23a, zA + k * 4);
                    LDS2U64(Z01b, Z23b, zB + k * 4);
                    #pragma unroll
                    for (int j = 0; j < 4; j++) {
                        unsigned long long W01, W23;
                        LDS2U64(W01, W23, wbase + (uint32_t)(j * WJ + k) * 4u);
                        FMA2(A[j][0], W01, Z01a); FMA2(A[j][0], W23, Z23a);
                        FMA2(A[j][1], W01, Z01b); FMA2(A[j][1], W23, Z23b);
                    }
                }
            }
        }
    }

    // final frozen h == reference out[:, -1, :]
    if (tid < 128) out[bg * HID + uu] = h_r;
}

extern "C" void kernel_launch(void* const* d_in, const int* in_sizes, int n_in,
                              void* d_out, int out_size) {
    const int*   x       = (const int*)d_in[0];
    const int*   lengths = (const int*)d_in[1];
    const float* emb     = (const float*)d_in[2];
    const float* W_ih    = (const float*)d_in[3];
    const float* W_hh    = (const float*)d_in[4];
    const float* b_ih    = (const float*)d_in[5];
    const float* b_hh    = (const float*)d_in[6];
    float* out = (float*)d_out;

    const int smem_bytes =
        (9408 + BPC * ZPAD + NSEG * GSEG + NROWS) * (int)sizeof(float)
        + (NB + 1) * (int)sizeof(int) + 32;

    cudaFuncSetAttribute(lstm_persist_kernel,
                         cudaFuncAttributeMaxDynamicSharedMemorySize, smem_bytes);

    lstm_init_kernel<<<1, 128>>>();
    lstm_persist_kernel<<<NCTA, NTHREADS, smem_bytes>>>(
        x, lengths, emb, W_ih, W_hh, b_ih, b_hh, out);
}

// round 12
// speedup vs baseline: 2.0569x; 1.1691x over previous
#include <cuda_runtime.h>
#include <cstdint>

// Problem constants
#define NB   64
#define NT   2048
#define EMBD 32
#define HID  256
#define KTOT (EMBD + HID)    // 288
#define USLICE 16            // unit slices (producers per group)
#define BSLICE 8             // batch slices
#define NCTA  (USLICE * BSLICE)   // 128
#define UPC   16             // units per CTA
#define NROWS (4 * UPC)      // 64 gate rows
#define BPC   (NB / BSLICE)  // 8 batches per CTA
#define NTHREADS 256         // 4 k-segments x (16 rg x 4 bq)
#define NSEG 4
#define SEGK 64

#define WJ   292             // j stride (floats), 16B-aligned
#define WRG  1188            // rg stride; %32==4 -> 8 rg/warp tile all banks; 16B-aligned
#define ZPAD 296             // z row stride; %32==8 -> 4 batch rows on banks 0/8/16/24
#define GSTR 9               // partial-gate row stride
#define GSEG (NROWS * GSTR)  // 576

// SMEM float offsets
#define W_F   0
#define W_SZ  (15 * WRG + 3 * WJ + KTOT)   // 18984 -> round up
#define Z_F   18992
#define GP_F  (Z_F + BPC * ZPAD)           // 18992 + 2368 = 21360
#define BS_F  (GP_F + NSEG * GSEG)         // 21360 + 2304 = 23664
#define LEN_F (BS_F + NROWS)               // 23728
#define ML_F  (LEN_F + NB)                 // 23792
#define SM_FLOATS (ML_F + 4)

// Persistent cross-CTA state
__device__ float g_H[2][NB * HID];        // [buf][batch*HID + unit]
__device__ int   g_flag[BSLICE][USLICE];  // steps completed by producer (us,bsl)

__global__ void lstm_init_kernel() {
    int i = threadIdx.x;
    if (i < BSLICE * USLICE) ((int*)g_flag)[i] = 0;
}

__device__ __forceinline__ float sigf(float x)  { return 1.0f / (1.0f + __expf(-x)); }
__device__ __forceinline__ float tanha(float x) { return 2.0f / (1.0f + __expf(-2.0f * x)) - 1.0f; }

__device__ __forceinline__ int ld_acq(const int* p) {
    int v;
    asm volatile("ld.acquire.gpu.b32 %0, [%1];" : "=r"(v) : "l"(p));
    return v;
}

#define LDS2U64(a, b, addr) \
    asm volatile("ld.shared.v2.u64 {%0,%1}, [%2];" : "=l"(a), "=l"(b) : "r"(addr))
#define FMA2(acc, w, z) \
    asm volatile("fma.rn.f32x2 %0, %1, %2, %0;" : "+l"(acc) : "l"(w), "l"(z))

__global__ void __launch_bounds__(NTHREADS, 1)
lstm_persist_kernel(const int* __restrict__ x,        // [NB, NT]
                    const int* __restrict__ lengths,  // [NB]
                    const float* __restrict__ emb,    // [VOCAB, EMBD]
                    const float* __restrict__ W_ih,   // [4*HID, EMBD]
                    const float* __restrict__ W_hh,   // [4*HID, HID]
                    const float* __restrict__ b_ih,   // [4*HID]
                    const float* __restrict__ b_hh,   // [4*HID]
                    float* __restrict__ out)          // [NB, 1, HID]
{
    extern __shared__ float sm[];
    float* w_s  = sm + W_F;                  // [rg 0..15][j 0..3][k 0..287]
    float* z_s  = sm + Z_F;                  // [BPC][ZPAD]  k: 0..31 xe, 32..287 h
    float* gp   = sm + GP_F;                 // [NSEG][NROWS][GSTR]
    float* bs   = sm + BS_F;                 // [NROWS]
    int* lenS   = (int*)(sm + LEN_F);        // [NB]
    int* mlS    = (int*)(sm + ML_F);

    const int tid = threadIdx.x;
    const int cta = blockIdx.x;
    const int us  = cta & (USLICE - 1);      // 0..15
    const int bsl = cta >> 4;                // 0..7
    const int u0  = us * UPC;
    const int bb0 = bsl * BPC;

    // ---- one-time staging ----
    for (int idx = tid; idx < NROWS * KTOT; idx += NTHREADS) {
        int r = idx / KTOT;
        int k = idx - r * KTOT;
        int g = r >> 4, du = r & 15;         // row r = g*16 + du
        int grow = g * HID + u0 + du;
        float v = (k < EMBD) ? W_ih[grow * EMBD + k]
                             : W_hh[grow * HID + (k - EMBD)];
        w_s[(r >> 2) * WRG + (r & 3) * WJ + k] = v;
    }
    if (tid < NROWS) {
        int g = tid >> 4, du = tid & 15;
        int grow = g * HID + u0 + du;
        bs[tid] = b_ih[grow] + b_hh[grow];
    }
    if (tid < NB) lenS[tid] = lengths[tid];
    __syncthreads();
    if (tid == 0) {
        int m = 1;
        for (int b = 0; b < NB; b++) m = max(m, lenS[b]);
        *mlS = m;
    }
    // zero h region of z (t=0 reads zeros)
    for (int i = tid; i < BPC * HID; i += NTHREADS) {
        int b = i >> 8, u = i & 255;
        z_s[b * ZPAD + EMBD + u] = 0.0f;
    }
    // gather xe(0)
    if (tid < BPC) {
        int tok = x[(bb0 + tid) * NT + 0];
        const float4* e = (const float4*)(emb + (long)tok * EMBD);
        float4* zr = (float4*)(z_s + tid * ZPAD);
        #pragma unroll
        for (int q = 0; q < EMBD / 4; q++) zr[q] = e[q];
    }
    __syncthreads();
    const int maxlen = *mlS;

    // shared base for asm addressing
    uint32_t sb;
    asm("{ .reg .u64 t; cvta.to.shared.u64 t, %1; cvt.u32.u64 %0, t; }"
        : "=r"(sb) : "l"(sm));

    // GEMM mapping: tid = seg*64 + rg*4 + bq
    const int seg = tid >> 6;                // 0..3
    const int rg  = (tid >> 2) & 15;         // rows 4rg..4rg+3
    const int bq  = tid & 3;                 // batches bq, bq+4
    const uint32_t wbase = sb + (uint32_t)(W_F + rg * WRG) * 4u;
    const uint32_t wk    = wbase + (uint32_t)(EMBD + seg * SEGK) * 4u;
    const uint32_t zA    = sb + (uint32_t)(Z_F + bq * ZPAD) * 4u;
    const uint32_t zB    = zA + (uint32_t)(4 * ZPAD) * 4u;
    const uint32_t zkA   = zA + (uint32_t)(EMBD + seg * SEGK) * 4u;
    const uint32_t zkB   = zB + (uint32_t)(EMBD + seg * SEGK) * 4u;
    float* gpb = gp + seg * GSEG;

    // phase-2 mapping (tid < 128): unit u_l = tid>>3 (0..15), batch b2 = tid&7
    const int u_l = tid >> 3;
    const int b2  = tid & 7;
    const int bg  = bb0 + b2;
    const int uu  = u0 + (u_l & 15);
    const int mylen = (tid < 128) ? lenS[bg] : 0;
    float c_r = 0.0f, h_r = 0.0f;

    // staging mapping: 2 float4 per thread
    const int sidx0 = tid;                   // 0..255
    const int sidx1 = tid + 256;             // 256..511

    unsigned long long A[4][2];
    #pragma unroll
    for (int j = 0; j < 4; j++) { A[j][0] = 0ull; A[j][1] = 0ull; }

    // ---- prologue: seg0 accumulates W_ih . xe(0) ----
    if (seg == 0) {
        #pragma unroll
        for (int k = 0; k < EMBD; k += 4) {
            unsigned long long Z01a, Z23a, Z01b, Z23b;
            LDS2U64(Z01a, Z23a, zA + k * 4);
            LDS2U64(Z01b, Z23b, zB + k * 4);
            #pragma unroll
            for (int j = 0; j < 4; j++) {
                unsigned long long W01, W23;
                LDS2U64(W01, W23, wbase + (uint32_t)(j * WJ + k) * 4u);
                FMA2(A[j][0], W01, Z01a); FMA2(A[j][0], W23, Z23a);
                FMA2(A[j][1], W01, Z01b); FMA2(A[j][1], W23, Z23b);
            }
        }
    }

    for (int t = 0; t < maxlen; t++) {
        // ---- partial acc += W_hh . h over my 64-k segment ----
        #pragma unroll 4
        for (int k = 0; k < SEGK; k += 4) {
            unsigned long long Z01a, Z23a, Z01b, Z23b;
            LDS2U64(Z01a, Z23a, zkA + k * 4);
            LDS2U64(Z01b, Z23b, zkB + k * 4);
            #pragma unroll
            for (int j = 0; j < 4; j++) {
                unsigned long long W01, W23;
                LDS2U64(W01, W23, wk + (uint32_t)(j * WJ + k) * 4u);
                FMA2(A[j][0], W01, Z01a); FMA2(A[j][0], W23, Z23a);
                FMA2(A[j][1], W01, Z01b); FMA2(A[j][1], W23, Z23b);
            }
        }
        // write partial gate sums (lo+hi of k-split accumulators)
        #pragma unroll
        for (int j = 0; j < 4; j++) {
            float ga = __uint_as_float((uint32_t)A[j][0]) +
                       __uint_as_float((uint32_t)(A[j][0] >> 32));
            float gb = __uint_as_float((uint32_t)A[j][1]) +
                       __uint_as_float((uint32_t)(A[j][1] >> 32));
            gpb[(4 * rg + j) * GSTR + bq]     = ga;
            gpb[(4 * rg + j) * GSTR + bq + 4] = gb;
        }
        __syncthreads();

        // ---- phase 2 (tid < 128): reduce 4 partials + bias, activations ----
        if (tid < 128) {
            float gate[4];
            #pragma unroll
            for (int g = 0; g < 4; g++) {
                int r = g * UPC + u_l;
                float s = bs[r];
                #pragma unroll
                for (int sg = 0; sg < NSEG; sg++)
                    s += gp[sg * GSEG + r * GSTR + b2];
                gate[g] = s;
            }
            float iv = sigf(gate[0]), fv = sigf(gate[1]);
            float gv = tanha(gate[2]), ov = sigf(gate[3]);
            float cn = fmaf(fv, c_r, iv * gv);
            float hn = ov * tanha(cn);
            if (t < mylen) { c_r = cn; h_r = hn; }
            g_H[(t + 1) & 1][bg * HID + uu] = h_r;
        }
        __syncthreads();   // all g_H stores issued CTA-wide

        // ---- publish: release-store orders prior global writes ----
        if (tid == 0) {
            asm volatile("st.release.gpu.b32 [%0], %1;"
                         :: "l"(&g_flag[bsl][us]), "r"(t + 1) : "memory");
        }

        if (t + 1 < maxlen) {
            // gather xe(t+1) (read by input GEMM after the bar below)
            if (tid < BPC) {
                int tok = x[(bb0 + tid) * NT + (t + 1)];
                const float4* e = (const float4*)(emb + (long)tok * EMBD);
                float4* zr = (float4*)(z_s + tid * ZPAD);
                #pragma unroll
                for (int q = 0; q < EMBD / 4; q++) zr[q] = e[q];
            }
            // tight acquire spin on the 16 producers of my group
            if (tid < USLICE) {
                const int* f = &g_flag[bsl][tid];
                while (ld_acq(f) < t + 1) { }
            }
            __syncthreads();

            // prefetch h(t) fragments (latency covered by input GEMM below)
            float4 p0, p1;
            {
                const float4* src = (const float4*)(g_H[(t + 1) & 1] + bb0 * HID);
                asm volatile("ld.volatile.global.v4.f32 {%0,%1,%2,%3}, [%4];"
                             : "=f"(p0.x), "=f"(p0.y), "=f"(p0.z), "=f"(p0.w)
                             : "l"(src + sidx0));
                asm volatile("ld.volatile.global.v4.f32 {%0,%1,%2,%3}, [%4];"
                             : "=f"(p1.x), "=f"(p1.y), "=f"(p1.z), "=f"(p1.w)
                             : "l"(src + sidx1));
            }
            // reset partials; seg0 folds in the xe GEMM for t+1
            #pragma unroll
            for (int j = 0; j < 4; j++) { A[j][0] = 0ull; A[j][1] = 0ull; }
            if (seg == 0) {
                #pragma unroll
                for (int k = 0; k < EMBD; k += 4) {
                    unsigned long long Z01a, Z23a, Z01b, Z23b;
                    LDS2U64(Z01a, Z23a, zA + k * 4);
                    LDS2U64(Z01b, Z23b, zB + k * 4);
                    #pragma unroll
                    for (int j = 0; j < 4; j++) {
                        unsigned long long W01, W23;
                        LDS2U64(W01, W23, wbase + (uint32_t)(j * WJ + k) * 4u);
                        FMA2(A[j][0], W01, Z01a); FMA2(A[j][0], W23, Z23a);
                        FMA2(A[j][1], W01, Z01b); FMA2(A[j][1], W23, Z23b);
                    }
                }
            }
            // STS the prefetched h fragments
            {
                int b0i = sidx0 >> 6, u40 = (sidx0 & 63) * 4;
                int b1i = sidx1 >> 6, u41 = (sidx1 & 63) * 4;
                *(float4*)(z_s + b0i * ZPAD + EMBD + u40) = p0;
                *(float4*)(z_s + b1i * ZPAD + EMBD + u41) = p1;
            }
            __syncthreads();
        }
    }

    // final frozen h == reference out[:, -1, :]
    if (tid < 128) out[bg * HID + uu] = h_r;
}

extern "C" void kernel_launch(void* const* d_in, const int* in_sizes, int n_in,
                              void* d_out, int out_size) {
    const int*   x       = (const int*)d_in[0];
    const int*   lengths = (const int*)d_in[1];
    const float* emb     = (const float*)d_in[2];
    const float* W_ih    = (const float*)d_in[3];
    const float* W_hh    = (const float*)d_in[4];
    const float* b_ih    = (const float*)d_in[5];
    const float* b_hh    = (const float*)d_in[6];
    float* out = (float*)d_out;

    const int smem_bytes = SM_FLOATS * (int)sizeof(float) + 32;

    cudaFuncSetAttribute(lstm_persist_kernel,
                         cudaFuncAttributeMaxDynamicSharedMemorySize, smem_bytes);

    lstm_init_kernel<<<1, 128>>>();
    lstm_persist_kernel<<<NCTA, NTHREADS, smem_bytes>>>(
        x, lengths, emb, W_ih, W_hh, b_ih, b_hh, out);
}

// round 13
// speedup vs baseline: 2.2416x; 1.0898x over previous
#include <cuda_runtime.h>
#include <cstdint>

// Problem constants
#define NB   64
#define NT   2048
#define EMBD 32
#define HID  256
#define KTOT (EMBD + HID)    // 288
#define USLICE 8             // unit slices (producers per group)
#define BSLICE 16            // batch slices
#define NCTA  (USLICE * BSLICE)   // 128
#define UPC   32             // units per CTA
#define NROWS (4 * UPC)      // 128 gate rows
#define BPC   (NB / BSLICE)  // 4 batches per CTA
#define NTHREADS 256         // 4 k-segments x (32 rg x 2 bq)
#define NSEG 4
#define SEGK 64

#define WJ   292             // j stride (floats), 16B-aligned
#define WRG  1188            // rg stride; %32==4; 16B-aligned
#define ZPAD 296             // z row stride; %32==8; 16B-aligned
#define GSTR 9               // partial-gate row stride
#define GSEG (NROWS * GSTR)  // 1152

// SMEM float offsets
#define W_F   0
// W size = 31*WRG + 3*WJ + KTOT = 37992 -> round to 38000
#define Z_F   38000
#define GP_F  (Z_F + BPC * ZPAD)           // 38000 + 1184 = 39184
#define BS_F  (GP_F + NSEG * GSEG)         // 39184 + 4608 = 43792
#define LEN_F (BS_F + NROWS)               // 43920
#define ML_F  (LEN_F + NB)                 // 43984
#define SM_FLOATS (ML_F + 4)               // 43988 (~176 KB)

// Persistent cross-CTA state
__device__ float g_H[2][NB * HID];        // [buf][batch*HID + unit]
__device__ int   g_flag[BSLICE][USLICE];  // steps completed by producer (us,bsl)

__global__ void lstm_init_kernel() {
    int i = threadIdx.x;
    if (i < BSLICE * USLICE) ((int*)g_flag)[i] = 0;
}

__device__ __forceinline__ float sigf(float x)  { return 1.0f / (1.0f + __expf(-x)); }
__device__ __forceinline__ float tanha(float x) { return 2.0f / (1.0f + __expf(-2.0f * x)) - 1.0f; }

__device__ __forceinline__ int ld_acq(const int* p) {
    int v;
    asm volatile("ld.acquire.gpu.b32 %0, [%1];" : "=r"(v) : "l"(p));
    return v;
}

#define LDS2U64(a, b, addr) \
    asm volatile("ld.shared.v2.u64 {%0,%1}, [%2];" : "=l"(a), "=l"(b) : "r"(addr))
#define FMA2(acc, w, z) \
    asm volatile("fma.rn.f32x2 %0, %1, %2, %0;" : "+l"(acc) : "l"(w), "l"(z))

__global__ void __launch_bounds__(NTHREADS, 1)
lstm_persist_kernel(const int* __restrict__ x,        // [NB, NT]
                    const int* __restrict__ lengths,  // [NB]
                    const float* __restrict__ emb,    // [VOCAB, EMBD]
                    const float* __restrict__ W_ih,   // [4*HID, EMBD]
                    const float* __restrict__ W_hh,   // [4*HID, HID]
                    const float* __restrict__ b_ih,   // [4*HID]
                    const float* __restrict__ b_hh,   // [4*HID]
                    float* __restrict__ out)          // [NB, 1, HID]
{
    extern __shared__ float sm[];
    float* w_s  = sm + W_F;                  // [rg 0..31][j 0..3][k 0..287]
    float* z_s  = sm + Z_F;                  // [BPC][ZPAD]  k: 0..31 xe, 32..287 h
    float* gp   = sm + GP_F;                 // [NSEG][NROWS][GSTR]
    float* bs   = sm + BS_F;                 // [NROWS]
    int* lenS   = (int*)(sm + LEN_F);        // [NB]
    int* mlS    = (int*)(sm + ML_F);

    const int tid = threadIdx.x;
    const int cta = blockIdx.x;
    const int us  = cta & (USLICE - 1);      // 0..7
    const int bsl = cta >> 3;                // 0..15
    const int u0  = us * UPC;
    const int bb0 = bsl * BPC;

    // ---- one-time staging: W rows (row r = g*32 + du), biases, lengths ----
    for (int idx = tid; idx < NROWS * KTOT; idx += NTHREADS) {
        int r = idx / KTOT;
        int k = idx - r * KTOT;
        int g = r >> 5, du = r & 31;
        int grow = g * HID + u0 + du;
        float v = (k < EMBD) ? W_ih[grow * EMBD + k]
                             : W_hh[grow * HID + (k - EMBD)];
        w_s[(r >> 2) * WRG + (r & 3) * WJ + k] = v;
    }
    if (tid < NROWS) {
        int g = tid >> 5, du = tid & 31;
        int grow = g * HID + u0 + du;
        bs[tid] = b_ih[grow] + b_hh[grow];
    }
    if (tid < NB) lenS[tid] = lengths[tid];
    __syncthreads();
    if (tid == 0) {
        int m = 1;
        for (int b = 0; b < NB; b++) m = max(m, lenS[b]);
        *mlS = m;
    }
    // zero h region of z (t=0 reads zeros)
    for (int i = tid; i < BPC * HID; i += NTHREADS) {
        int b = i >> 8, u = i & 255;
        z_s[b * ZPAD + EMBD + u] = 0.0f;
    }
    // gather xe(0): tid<32 -> batch tid>>3, float4 q = tid&7
    if (tid < 8 * BPC) {
        int b = tid >> 3, q = tid & 7;
        int tok = x[(bb0 + b) * NT + 0];
        float4 v = ((const float4*)(emb + (size_t)tok * EMBD))[q];
        *(float4*)(z_s + b * ZPAD + q * 4) = v;
    }
    __syncthreads();
    const int maxlen = *mlS;

    // shared base for asm addressing
    uint32_t sb;
    asm("{ .reg .u64 t; cvta.to.shared.u64 t, %1; cvt.u32.u64 %0, t; }"
        : "=r"(sb) : "l"(sm));

    // GEMM mapping: tid = seg*64 + rg*2 + bq
    const int seg = tid >> 6;                // 0..3
    const int rg  = (tid >> 1) & 31;         // rows 4rg..4rg+3
    const int bq  = tid & 1;                 // batches bq, bq+2
    const uint32_t wbase = sb + (uint32_t)(W_F + rg * WRG) * 4u;
    const uint32_t wk    = wbase + (uint32_t)(EMBD + seg * SEGK) * 4u;
    const uint32_t zA    = sb + (uint32_t)(Z_F + bq * ZPAD) * 4u;
    const uint32_t zB    = zA + (uint32_t)(2 * ZPAD) * 4u;
    const uint32_t zkA   = zA + (uint32_t)(EMBD + seg * SEGK) * 4u;
    const uint32_t zkB   = zB + (uint32_t)(EMBD + seg * SEGK) * 4u;
    float* gpb = gp + seg * GSEG;

    // phase-2 mapping (tid < 128): unit u_l = tid>>2 (0..31), batch b2 = tid&3
    const int u_l = tid >> 2;
    const int b2  = tid & 3;
    const int bg  = bb0 + (b2 & 3);
    const int uu  = u0 + (u_l & 31);
    const int mylen = (tid < 128) ? lenS[bg] : 0;
    float c_r = 0.0f, h_r = 0.0f;

    unsigned long long A[4][2];
    #pragma unroll
    for (int j = 0; j < 4; j++) { A[j][0] = 0ull; A[j][1] = 0ull; }

    // ---- prologue: seg0 accumulates W_ih . xe(0) ----
    if (seg == 0) {
        #pragma unroll
        for (int k = 0; k < EMBD; k += 4) {
            unsigned long long Z01a, Z23a, Z01b, Z23b;
            LDS2U64(Z01a, Z23a, zA + k * 4);
            LDS2U64(Z01b, Z23b, zB + k * 4);
            #pragma unroll
            for (int j = 0; j < 4; j++) {
                unsigned long long W01, W23;
                LDS2U64(W01, W23, wbase + (uint32_t)(j * WJ + k) * 4u);
                FMA2(A[j][0], W01, Z01a); FMA2(A[j][0], W23, Z23a);
                FMA2(A[j][1], W01, Z01b); FMA2(A[j][1], W23, Z23b);
            }
        }
    }

    for (int t = 0; t < maxlen; t++) {
        // ---- partial acc += W_hh . h over my 64-k segment ----
        #pragma unroll 4
        for (int k = 0; k < SEGK; k += 4) {
            unsigned long long Z01a, Z23a, Z01b, Z23b;
            LDS2U64(Z01a, Z23a, zkA + k * 4);
            LDS2U64(Z01b, Z23b, zkB + k * 4);
            #pragma unroll
            for (int j = 0; j < 4; j++) {
                unsigned long long W01, W23;
                LDS2U64(W01, W23, wk + (uint32_t)(j * WJ + k) * 4u);
                FMA2(A[j][0], W01, Z01a); FMA2(A[j][0], W23, Z23a);
                FMA2(A[j][1], W01, Z01b); FMA2(A[j][1], W23, Z23b);
            }
        }
        // write partial gate sums (lo+hi of k-split accumulators)
        #pragma unroll
        for (int j = 0; j < 4; j++) {
            float ga = __uint_as_float((uint32_t)A[j][0]) +
                       __uint_as_float((uint32_t)(A[j][0] >> 32));
            float gb = __uint_as_float((uint32_t)A[j][1]) +
                       __uint_as_float((uint32_t)(A[j][1] >> 32));
            gpb[(4 * rg + j) * GSTR + bq]     = ga;
            gpb[(4 * rg + j) * GSTR + bq + 2] = gb;
        }
        __syncthreads();

        // ---- phase 2 (tid < 128): reduce 4 partials + bias, activations ----
        if (tid < 128) {
            float gate[4];
            #pragma unroll
            for (int g = 0; g < 4; g++) {
                int r = g * UPC + u_l;
                float s = bs[r];
                #pragma unroll
                for (int sg = 0; sg < NSEG; sg++)
                    s += gp[sg * GSEG + r * GSTR + b2];
                gate[g] = s;
            }
            float iv = sigf(gate[0]), fv = sigf(gate[1]);
            float gv = tanha(gate[2]), ov = sigf(gate[3]);
            float cn = fmaf(fv, c_r, iv * gv);
            float hn = ov * tanha(cn);
            if (t < mylen) { c_r = cn; h_r = hn; }
            g_H[(t + 1) & 1][bg * HID + uu] = h_r;
        }
        __syncthreads();   // all g_H stores issued CTA-wide

        // ---- publish: release-store orders prior global writes ----
        if (tid == 0) {
            asm volatile("st.release.gpu.b32 [%0], %1;"
                         :: "l"(&g_flag[bsl][us]), "r"(t + 1) : "memory");
        }

        if (t + 1 < maxlen) {
            // gather xe(t+1)
            if (tid < 8 * BPC) {
                int b = tid >> 3, q = tid & 7;
                int tok = x[(bb0 + b) * NT + (t + 1)];
                float4 v = ((const float4*)(emb + (size_t)tok * EMBD))[q];
                *(float4*)(z_s + b * ZPAD + q * 4) = v;
            }
            // tight acquire spin on the 8 producers of my group
            if (tid < USLICE) {
                const int* f = &g_flag[bsl][tid];
                while (ld_acq(f) < t + 1) { }
            }
            __syncthreads();

            // prefetch h(t): one float4 per thread (covered by input GEMM)
            float4 p0;
            {
                const float4* src = (const float4*)(g_H[(t + 1) & 1] + bb0 * HID);
                asm volatile("ld.volatile.global.v4.f32 {%0,%1,%2,%3}, [%4];"
                             : "=f"(p0.x), "=f"(p0.y), "=f"(p0.z), "=f"(p0.w)
                             : "l"(src + tid));
            }
            // reset partials; seg0 folds in the xe GEMM for t+1
            #pragma unroll
            for (int j = 0; j < 4; j++) { A[j][0] = 0ull; A[j][1] = 0ull; }
            if (seg == 0) {
                #pragma unroll
                for (int k = 0; k < EMBD; k += 4) {
                    unsigned long long Z01a, Z23a, Z01b, Z23b;
                    LDS2U64(Z01a, Z23a, zA + k * 4);
                    LDS2U64(Z01b, Z23b, zB + k * 4);
                    #pragma unroll
                    for (int j = 0; j < 4; j++) {
                        unsigned long long W01, W23;
                        LDS2U64(W01, W23, wbase + (uint32_t)(j * WJ + k) * 4u);
                        FMA2(A[j][0], W01, Z01a); FMA2(A[j][0], W23, Z23a);
                        FMA2(A[j][1], W01, Z01b); FMA2(A[j][1], W23, Z23b);
                    }
                }
            }
            // STS the prefetched h fragment
            {
                int b0i = tid >> 6;                 // 0..3
                int u40 = (tid & 63) * 4;           // 0..252
                *(float4*)(z_s + b0i * ZPAD + EMBD + u40) = p0;
            }
            __syncthreads();
        }
    }

    // final frozen h == reference out[:, -1, :]
    if (tid < 128) out[bg * HID + uu] = h_r;
}

extern "C" void kernel_launch(void* const* d_in, const int* in_sizes, int n_in,
                              void* d_out, int out_size) {
    const int*   x       = (const int*)d_in[0];
    const int*   lengths = (const int*)d_in[1];
    const float* emb     = (const float*)d_in[2];
    const float* W_ih    = (const float*)d_in[3];
    const float* W_hh    = (const float*)d_in[4];
    const float* b_ih    = (const float*)d_in[5];
    const float* b_hh    = (const float*)d_in[6];
    float* out = (float*)d_out;

    const int smem_bytes = SM_FLOATS * (int)sizeof(float) + 32;

    cudaFuncSetAttribute(lstm_persist_kernel,
                         cudaFuncAttributeMaxDynamicSharedMemorySize, smem_bytes);

    lstm_init_kernel<<<1, 128>>>();
    lstm_persist_kernel<<<NCTA, NTHREADS, smem_bytes>>>(
        x, lengths, emb, W_ih, W_hh, b_ih, b_hh, out);
}